// round 4
// baseline (speedup 1.0000x reference)
#include <cuda_runtime.h>
#include <math.h>

// VectorKNN: top-5 inner products of normalized query [1,256] vs bank [1M,256] fp32.
// Strategy: warp-per-row coalesced streaming (HBM-bound, ~1.024 GB/launch),
// register-resident top-5 per warp, block merge, tiny final merge kernel.
// Ranking uses RAW dots (query norm is a positive monotone scale); final values
// are scaled by 1/max(||q||, eps) to match torch F.normalize semantics.

#define D        256
#define KTOP     5
#define BLOCK    256
#define GRID     1184
#define WPB      (BLOCK / 32)
#define TOTWARPS (GRID * WPB)

__device__ float g_inv_norm;
__device__ float g_bvals[GRID * KTOP];
__device__ int   g_bidx [GRID * KTOP];

// Insert (v, id) into descending sorted top-K held in registers.
// Strict '>' keeps earlier (lower-index) entries ahead on ties, matching top_k.
__device__ __forceinline__ void topk_insert(float* vals, int* idxs, float v, int id) {
    if (v > vals[KTOP - 1]) {
        vals[KTOP - 1] = v;
        idxs[KTOP - 1] = id;
#pragma unroll
        for (int i = KTOP - 2; i >= 0; i--) {
            if (vals[i + 1] > vals[i]) {
                float tv = vals[i]; vals[i] = vals[i + 1]; vals[i + 1] = tv;
                int   ti = idxs[i]; idxs[i] = idxs[i + 1]; idxs[i + 1] = ti;
            }
        }
    }
}

// ---------------- Kernel 1: query inverse norm (1 warp) ----------------
__global__ void qnorm_kernel(const float* __restrict__ q) {
    int lane = threadIdx.x;
    float s = 0.f;
#pragma unroll
    for (int i = 0; i < D / 32; i++) {
        float v = q[lane * (D / 32) + i];
        s = fmaf(v, v, s);
    }
#pragma unroll
    for (int o = 16; o; o >>= 1) s += __shfl_xor_sync(0xFFFFFFFFu, s, o);
    if (lane == 0) g_inv_norm = 1.0f / fmaxf(sqrtf(s), 1e-12f);
}

// ---------------- Kernel 2: streaming dot + per-block top-5 ----------------
__global__ void __launch_bounds__(BLOCK) dot_topk_kernel(
    const float*  __restrict__ q,
    const float4* __restrict__ emb,   // [N * 64] float4
    int n)
{
    __shared__ float4 sq[D / 4];
    int tid = threadIdx.x;
    if (tid < D / 4) sq[tid] = ((const float4*)q)[tid];
    __syncthreads();

    int lane = tid & 31;
    int wid  = tid >> 5;
    int gw   = blockIdx.x * WPB + wid;

    float4 q0 = sq[lane * 2];
    float4 q1 = sq[lane * 2 + 1];

    float vals[KTOP];
    int   idxs[KTOP];
#pragma unroll
    for (int i = 0; i < KTOP; i++) { vals[i] = -INFINITY; idxs[i] = -1; }

    for (int row = gw; row < n; row += TOTWARPS) {
        const float4* r = emb + (size_t)row * (D / 4);
        float4 a = r[lane * 2];
        float4 b = r[lane * 2 + 1];
        float s = 0.f;
        s = fmaf(a.x, q0.x, s); s = fmaf(a.y, q0.y, s);
        s = fmaf(a.z, q0.z, s); s = fmaf(a.w, q0.w, s);
        s = fmaf(b.x, q1.x, s); s = fmaf(b.y, q1.y, s);
        s = fmaf(b.z, q1.z, s); s = fmaf(b.w, q1.w, s);
#pragma unroll
        for (int o = 16; o; o >>= 1) s += __shfl_xor_sync(0xFFFFFFFFu, s, o);
        // all lanes hold identical s -> identical top-5, zero divergence
        topk_insert(vals, idxs, s, row);
    }

    __shared__ float sv[WPB * KTOP];
    __shared__ int   si[WPB * KTOP];
    if (lane == 0) {
#pragma unroll
        for (int i = 0; i < KTOP; i++) {
            sv[wid * KTOP + i] = vals[i];
            si[wid * KTOP + i] = idxs[i];
        }
    }
    __syncthreads();

    if (tid == 0) {
        float bv[KTOP]; int bi[KTOP];
#pragma unroll
        for (int i = 0; i < KTOP; i++) { bv[i] = -INFINITY; bi[i] = -1; }
        for (int c = 0; c < WPB * KTOP; c++) topk_insert(bv, bi, sv[c], si[c]);
#pragma unroll
        for (int i = 0; i < KTOP; i++) {
            g_bvals[blockIdx.x * KTOP + i] = bv[i];
            g_bidx [blockIdx.x * KTOP + i] = bi[i];
        }
    }
}

// ---------------- Kernel 3: final merge (1 warp) ----------------
__global__ void final_merge_kernel(float* __restrict__ out) {
    int lane = threadIdx.x;
    float vals[KTOP]; int idxs[KTOP];
#pragma unroll
    for (int i = 0; i < KTOP; i++) { vals[i] = -INFINITY; idxs[i] = -1; }

    const int total = GRID * KTOP;
    for (int c = lane; c < total; c += 32)
        topk_insert(vals, idxs, g_bvals[c], g_bidx[c]);

    __shared__ float sv[32 * KTOP];
    __shared__ int   si[32 * KTOP];
#pragma unroll
    for (int i = 0; i < KTOP; i++) {
        sv[lane * KTOP + i] = vals[i];
        si[lane * KTOP + i] = idxs[i];
    }
    __syncwarp();

    if (lane == 0) {
        float bv[KTOP]; int bi[KTOP];
#pragma unroll
        for (int i = 0; i < KTOP; i++) { bv[i] = -INFINITY; bi[i] = -1; }
        for (int c = 0; c < 32 * KTOP; c++) topk_insert(bv, bi, sv[c], si[c]);
        float inv = g_inv_norm;
#pragma unroll
        for (int i = 0; i < KTOP; i++) {
            out[i]        = (float)bi[i];      // top_idx (flattened first)
            out[KTOP + i] = bv[i] * inv;       // top_vals (scaled by 1/||q||)
        }
    }
}

extern "C" void kernel_launch(void* const* d_in, const int* in_sizes, int n_in,
                              void* d_out, int out_size) {
    const float* q   = (const float*)d_in[0];   // [1, 256]
    const float* emb = (const float*)d_in[1];   // [1M, 256]
    int n = in_sizes[1] / D;

    qnorm_kernel<<<1, 32>>>(q);
    dot_topk_kernel<<<GRID, BLOCK>>>(q, (const float4*)emb, n);
    final_merge_kernel<<<1, 32>>>((float*)d_out);
}

// round 10
// speedup vs baseline: 1.4710x; 1.4710x over previous
#include <cuda_runtime.h>
#include <math.h>

// VectorKNN v2: top-5 inner products of normalized query [1,256] vs bank [1M,256] fp32.
// HBM-streaming, warp-per-row-pair, fully coalesced (lane / lane+32 float4 pattern),
// persistent single-wave grid (592 = 4 CTAs/SM x 148), register top-5, block merge,
// 1-warp final merge that also computes the query norm (ranking uses raw dots;
// final values scaled by 1/max(||q||,eps) to match F.normalize + top_k).

#define D      256
#define KTOP   5
#define BLOCK  256
#define GRID   592
#define WPB    (BLOCK / 32)
#define TOTW   (GRID * WPB)          // 4736 warps

__device__ float g_bvals[GRID * KTOP];
__device__ int   g_bidx [GRID * KTOP];

// Insert (v, id) into descending top-K. Strict '>' keeps earlier index on ties.
__device__ __forceinline__ void topk_insert(float* vals, int* idxs, float v, int id) {
    if (v > vals[KTOP - 1]) {
        vals[KTOP - 1] = v;
        idxs[KTOP - 1] = id;
#pragma unroll
        for (int i = KTOP - 2; i >= 0; i--) {
            if (vals[i + 1] > vals[i]) {
                float tv = vals[i]; vals[i] = vals[i + 1]; vals[i + 1] = tv;
                int   ti = idxs[i]; idxs[i] = idxs[i + 1]; idxs[i + 1] = ti;
            }
        }
    }
}

__device__ __forceinline__ float dot8(float4 a, float4 b, float4 qa, float4 qb) {
    float s = 0.f;
    s = fmaf(a.x, qa.x, s); s = fmaf(a.y, qa.y, s);
    s = fmaf(a.z, qa.z, s); s = fmaf(a.w, qa.w, s);
    s = fmaf(b.x, qb.x, s); s = fmaf(b.y, qb.y, s);
    s = fmaf(b.z, qb.z, s); s = fmaf(b.w, qb.w, s);
    return s;
}

// ---------------- Kernel 1: streaming dots + per-block top-5 ----------------
__global__ void __launch_bounds__(BLOCK, 4) dot_topk_kernel(
    const float*  __restrict__ q,
    const float4* __restrict__ emb,   // [N * 64] float4
    int n)
{
    __shared__ float4 sq[D / 4];
    int tid = threadIdx.x;
    if (tid < D / 4) sq[tid] = ((const float4*)q)[tid];
    __syncthreads();

    int lane = tid & 31;
    int wid  = tid >> 5;
    int gw   = blockIdx.x * WPB + wid;

    // lane L handles row bytes [16L,16L+16) and [16L+512, 16L+528): fully
    // coalesced 512B per LDG.128 across the warp.
    float4 qa = sq[lane];
    float4 qb = sq[lane + 32];

    float vals[KTOP];
    int   idxs[KTOP];
#pragma unroll
    for (int i = 0; i < KTOP; i++) { vals[i] = -INFINITY; idxs[i] = -1; }

    // Each warp consumes a contiguous 2-row (2KB) pair per iteration.
    for (int base = gw * 2; base < n; base += TOTW * 2) {
        int r0 = base;
        int r1 = base + 1;
        const float4* p0 = emb + (size_t)r0 * (D / 4);
        const float4* p1 = p0 + ((r1 < n) ? (D / 4) : 0);

        float4 a0 = __ldcs(p0 + lane);
        float4 b0 = __ldcs(p0 + lane + 32);
        float4 a1 = __ldcs(p1 + lane);
        float4 b1 = __ldcs(p1 + lane + 32);

        float s0 = dot8(a0, b0, qa, qb);
        float s1 = dot8(a1, b1, qa, qb);

#pragma unroll
        for (int o = 16; o; o >>= 1) {
            s0 += __shfl_xor_sync(0xFFFFFFFFu, s0, o);
            s1 += __shfl_xor_sync(0xFFFFFFFFu, s1, o);
        }
        // all lanes hold identical sums -> identical top-5, zero divergence
        topk_insert(vals, idxs, s0, r0);
        if (r1 < n) topk_insert(vals, idxs, s1, r1);
    }

    __shared__ float sv[WPB * KTOP];
    __shared__ int   si[WPB * KTOP];
    if (lane == 0) {
#pragma unroll
        for (int i = 0; i < KTOP; i++) {
            sv[wid * KTOP + i] = vals[i];
            si[wid * KTOP + i] = idxs[i];
        }
    }
    __syncthreads();

    if (tid == 0) {
        float bv[KTOP]; int bi[KTOP];
#pragma unroll
        for (int i = 0; i < KTOP; i++) { bv[i] = -INFINITY; bi[i] = -1; }
        for (int c = 0; c < WPB * KTOP; c++) topk_insert(bv, bi, sv[c], si[c]);
#pragma unroll
        for (int i = 0; i < KTOP; i++) {
            g_bvals[blockIdx.x * KTOP + i] = bv[i];
            g_bidx [blockIdx.x * KTOP + i] = bi[i];
        }
    }
}

// ---------------- Kernel 2: final merge + query norm (1 warp) ----------------
__global__ void final_merge_kernel(const float* __restrict__ q, float* __restrict__ out) {
    int lane = threadIdx.x;

    // query inverse norm
    float ns = 0.f;
#pragma unroll
    for (int i = 0; i < D / 32; i++) {
        float v = q[lane * (D / 32) + i];
        ns = fmaf(v, v, ns);
    }
#pragma unroll
    for (int o = 16; o; o >>= 1) ns += __shfl_xor_sync(0xFFFFFFFFu, ns, o);
    float inv = 1.0f / fmaxf(sqrtf(ns), 1e-12f);

    float vals[KTOP]; int idxs[KTOP];
#pragma unroll
    for (int i = 0; i < KTOP; i++) { vals[i] = -INFINITY; idxs[i] = -1; }

    const int total = GRID * KTOP;
    for (int c = lane; c < total; c += 32)
        topk_insert(vals, idxs, g_bvals[c], g_bidx[c]);

    __shared__ float sv[32 * KTOP];
    __shared__ int   si[32 * KTOP];
#pragma unroll
    for (int i = 0; i < KTOP; i++) {
        sv[lane * KTOP + i] = vals[i];
        si[lane * KTOP + i] = idxs[i];
    }
    __syncwarp();

    if (lane == 0) {
        float bv[KTOP]; int bi[KTOP];
#pragma unroll
        for (int i = 0; i < KTOP; i++) { bv[i] = -INFINITY; bi[i] = -1; }
        for (int c = 0; c < 32 * KTOP; c++) topk_insert(bv, bi, sv[c], si[c]);
#pragma unroll
        for (int i = 0; i < KTOP; i++) {
            out[i]        = (float)bi[i];      // top_idx
            out[KTOP + i] = bv[i] * inv;       // top_vals (scaled by 1/||q||)
        }
    }
}

extern "C" void kernel_launch(void* const* d_in, const int* in_sizes, int n_in,
                              void* d_out, int out_size) {
    const float* q   = (const float*)d_in[0];   // [1, 256]
    const float* emb = (const float*)d_in[1];   // [1M, 256]
    int n = in_sizes[1] / D;

    dot_topk_kernel<<<GRID, BLOCK>>>(q, (const float4*)emb, n);
    final_merge_kernel<<<1, 32>>>(q, (float*)d_out);
}

// round 16
// speedup vs baseline: 1.6896x; 1.1487x over previous
#include <cuda_runtime.h>
#include <math.h>

// VectorKNN v3: top-5 inner products of normalized query [1,256] vs bank [1M,256] fp32.
// Single fused kernel: HBM-streaming warp-per-row-pair dots (one-wave persistent
// grid, fully coalesced lane/lane+32 float4 loads, __ldcs streaming), per-block
// top-5 to __device__ scratch, then the LAST block (threadfence-reduction
// pattern) merges all block results with 256 threads + shfl-based sorted-list
// merges and writes d_out. Ranking uses raw dots; final values scaled by
// 1/max(||q||,eps) to match F.normalize + top_k semantics.

#define D      256
#define KTOP   5
#define BLOCK  256
#define GRID   592
#define WPB    (BLOCK / 32)
#define TOTW   (GRID * WPB)          // 4736 warps
#define NCAND  (GRID * KTOP)         // 2960 block candidates

__device__ float        g_bvals[NCAND];
__device__ int          g_bidx [NCAND];
__device__ unsigned int g_done;      // 0 at load; reset to 0 by merging block

// Insert (v, id) into descending top-K. Strict '>' keeps earlier entry on ties.
__device__ __forceinline__ void topk_insert(float* vals, int* idxs, float v, int id) {
    if (v > vals[KTOP - 1]) {
        vals[KTOP - 1] = v;
        idxs[KTOP - 1] = id;
#pragma unroll
        for (int i = KTOP - 2; i >= 0; i--) {
            if (vals[i + 1] > vals[i]) {
                float tv = vals[i]; vals[i] = vals[i + 1]; vals[i + 1] = tv;
                int   ti = idxs[i]; idxs[i] = idxs[i + 1]; idxs[i + 1] = ti;
            }
        }
    }
}

// Butterfly merge of per-lane sorted top-5 lists across the full warp:
// after 5 steps every lane holds the warp-wide top-5.
__device__ __forceinline__ void warp_merge_top5(float* vals, int* idxs) {
#pragma unroll
    for (int o = 1; o < 32; o <<= 1) {
        float pv[KTOP]; int pi[KTOP];
#pragma unroll
        for (int i = 0; i < KTOP; i++) {
            pv[i] = __shfl_xor_sync(0xFFFFFFFFu, vals[i], o);
            pi[i] = __shfl_xor_sync(0xFFFFFFFFu, idxs[i], o);
        }
#pragma unroll
        for (int i = 0; i < KTOP; i++) topk_insert(vals, idxs, pv[i], pi[i]);
    }
}

__device__ __forceinline__ float dot8(float4 a, float4 b, float4 qa, float4 qb) {
    float s = 0.f;
    s = fmaf(a.x, qa.x, s); s = fmaf(a.y, qa.y, s);
    s = fmaf(a.z, qa.z, s); s = fmaf(a.w, qa.w, s);
    s = fmaf(b.x, qb.x, s); s = fmaf(b.y, qb.y, s);
    s = fmaf(b.z, qb.z, s); s = fmaf(b.w, qb.w, s);
    return s;
}

__global__ void __launch_bounds__(BLOCK, 4) knn_fused_kernel(
    const float*  __restrict__ q,
    const float4* __restrict__ emb,   // [N * 64] float4
    int n,
    float* __restrict__ out)
{
    __shared__ float4 sq[D / 4];
    int tid = threadIdx.x;
    if (tid < D / 4) sq[tid] = ((const float4*)q)[tid];
    __syncthreads();

    int lane = tid & 31;
    int wid  = tid >> 5;
    int gw   = blockIdx.x * WPB + wid;

    // lane L covers row bytes [16L,16L+16) and [16L+512,16L+528):
    // each LDG.128 is a fully-dense 512B warp transaction.
    float4 qa = sq[lane];
    float4 qb = sq[lane + 32];

    float vals[KTOP];
    int   idxs[KTOP];
#pragma unroll
    for (int i = 0; i < KTOP; i++) { vals[i] = -INFINITY; idxs[i] = -1; }

    // Each warp consumes a contiguous 2-row (2KB) pair per iteration.
    for (int base = gw * 2; base < n; base += TOTW * 2) {
        int r0 = base;
        int r1 = base + 1;
        const float4* p0 = emb + (size_t)r0 * (D / 4);
        const float4* p1 = p0 + ((r1 < n) ? (D / 4) : 0);

        float4 a0 = __ldcs(p0 + lane);
        float4 b0 = __ldcs(p0 + lane + 32);
        float4 a1 = __ldcs(p1 + lane);
        float4 b1 = __ldcs(p1 + lane + 32);

        float s0 = dot8(a0, b0, qa, qb);
        float s1 = dot8(a1, b1, qa, qb);

#pragma unroll
        for (int o = 16; o; o >>= 1) {
            s0 += __shfl_xor_sync(0xFFFFFFFFu, s0, o);
            s1 += __shfl_xor_sync(0xFFFFFFFFu, s1, o);
        }
        // all lanes hold identical sums -> identical top-5, zero divergence
        topk_insert(vals, idxs, s0, r0);
        if (r1 < n) topk_insert(vals, idxs, s1, r1);
    }

    // ---- per-block merge: 8 warp lists -> block top-5 -> scratch ----
    __shared__ float sv[WPB * KTOP];
    __shared__ int   si[WPB * KTOP];
    if (lane == 0) {
#pragma unroll
        for (int i = 0; i < KTOP; i++) {
            sv[wid * KTOP + i] = vals[i];
            si[wid * KTOP + i] = idxs[i];
        }
    }
    __syncthreads();

    if (tid == 0) {
        float bv[KTOP]; int bi[KTOP];
#pragma unroll
        for (int i = 0; i < KTOP; i++) { bv[i] = -INFINITY; bi[i] = -1; }
        for (int c = 0; c < WPB * KTOP; c++) topk_insert(bv, bi, sv[c], si[c]);
#pragma unroll
        for (int i = 0; i < KTOP; i++) {
            g_bvals[blockIdx.x * KTOP + i] = bv[i];
            g_bidx [blockIdx.x * KTOP + i] = bi[i];
        }
    }

    // ---- threadfence reduction: last block merges everything ----
    __threadfence();
    __shared__ unsigned int s_rank;
    if (tid == 0) s_rank = atomicAdd(&g_done, 1u);
    __syncthreads();

    if (s_rank == GRID - 1) {
        __threadfence();  // make all blocks' scratch writes visible

        float mv[KTOP]; int mi[KTOP];
#pragma unroll
        for (int i = 0; i < KTOP; i++) { mv[i] = -INFINITY; mi[i] = -1; }
        for (int c = tid; c < NCAND; c += BLOCK)
            topk_insert(mv, mi, g_bvals[c], g_bidx[c]);

        warp_merge_top5(mv, mi);      // each warp -> warp-wide top-5 in all lanes

        __shared__ float fv[WPB * KTOP];
        __shared__ int   fi[WPB * KTOP];
        if (lane == 0) {
#pragma unroll
            for (int i = 0; i < KTOP; i++) {
                fv[wid * KTOP + i] = mv[i];
                fi[wid * KTOP + i] = mi[i];
            }
        }
        __syncthreads();

        if (wid == 0) {
            float v2[KTOP]; int i2[KTOP];
#pragma unroll
            for (int i = 0; i < KTOP; i++) { v2[i] = -INFINITY; i2[i] = -1; }
            if (lane < WPB) {
#pragma unroll
                for (int i = 0; i < KTOP; i++) {
                    v2[i] = fv[lane * KTOP + i];
                    i2[i] = fi[lane * KTOP + i];
                }
            }
            warp_merge_top5(v2, i2);  // global top-5 in all lanes of warp 0

            // query inverse norm from the shared copy (no extra global reads)
            float4 na = sq[lane];
            float4 nb = sq[lane + 32];
            float ns = 0.f;
            ns = fmaf(na.x, na.x, ns); ns = fmaf(na.y, na.y, ns);
            ns = fmaf(na.z, na.z, ns); ns = fmaf(na.w, na.w, ns);
            ns = fmaf(nb.x, nb.x, ns); ns = fmaf(nb.y, nb.y, ns);
            ns = fmaf(nb.z, nb.z, ns); ns = fmaf(nb.w, nb.w, ns);
#pragma unroll
            for (int o = 16; o; o >>= 1) ns += __shfl_xor_sync(0xFFFFFFFFu, ns, o);

            if (lane == 0) {
                float inv = 1.0f / fmaxf(sqrtf(ns), 1e-12f);
#pragma unroll
                for (int i = 0; i < KTOP; i++) {
                    out[i]        = (float)i2[i];   // top_idx
                    out[KTOP + i] = v2[i] * inv;    // top_vals (scaled by 1/||q||)
                }
                g_done = 0;  // reset for next launch / graph replay
            }
        }
    }
}

extern "C" void kernel_launch(void* const* d_in, const int* in_sizes, int n_in,
                              void* d_out, int out_size) {
    const float* q   = (const float*)d_in[0];   // [1, 256]
    const float* emb = (const float*)d_in[1];   // [1M, 256]
    int n = in_sizes[1] / D;

    knn_fused_kernel<<<GRID, BLOCK>>>(q, (const float4*)emb, n, (float*)d_out);
}